// round 1
// baseline (speedup 1.0000x reference)
#include <cuda_runtime.h>
#include <math.h>

// ---------------------------------------------------------------------------
// CapsuleModel2: gather rows -> segment mean (sorted segment ids) -> GEMV ->
// sigmoid.
//   caps: [R, D] float32 (R = B*H*W), W: [D, NC], b: [NC]
//   point_idx: [P] int32 (flat row indices), segment_ids: [P] int32 sorted
//   out: [NI, NC] float32, NI = out_size / NC
// ---------------------------------------------------------------------------

#define MAX_SEGS (1 << 17)
__device__ int g_seg_off[MAX_SEGS + 1];   // g_seg_off[s] = first point of seg s

// O(P) boundary builder: segment_ids sorted ascending.
__global__ void seg_bounds_kernel(const int* __restrict__ seg, int P, int NI) {
    int p = blockIdx.x * blockDim.x + threadIdx.x;
    if (p >= P) return;
    int s = seg[p];
    if (p == 0) {
        for (int k = 0; k <= s; ++k) g_seg_off[k] = 0;
    } else {
        int prev = seg[p - 1];
        for (int k = prev + 1; k <= s; ++k) g_seg_off[k] = p;
    }
    if (p == P - 1) {
        for (int k = s + 1; k <= NI; ++k) g_seg_off[k] = P;
    }
}

// Vectorized path: D % 4 == 0 and D/4 <= BLOCK. One CTA per segment.
template <int BLOCK>
__global__ void __launch_bounds__(BLOCK)
capsule_vec_kernel(const float4* __restrict__ caps4,
                   const float* __restrict__ Wm,
                   const float* __restrict__ bias,
                   const int* __restrict__ pidx,
                   float* __restrict__ out,
                   int D4, int NC) {
    const int seg = blockIdx.x;
    const int tid = threadIdx.x;
    const int start = g_seg_off[seg];
    const int end   = g_seg_off[seg + 1];

    __shared__ int sidx[BLOCK];
    extern __shared__ float pooled[];   // D floats

    float4 acc = make_float4(0.f, 0.f, 0.f, 0.f);

    for (int base = start; base < end; base += BLOCK) {
        int n = min(BLOCK, end - base);
        if (tid < n) sidx[tid] = pidx[base + tid];
        __syncthreads();
        if (tid < D4) {
            int i = 0;
            // unroll-4: 4 independent LDG.128 in flight per thread
            for (; i + 4 <= n; i += 4) {
                const float4* r0 = caps4 + (size_t)sidx[i + 0] * D4;
                const float4* r1 = caps4 + (size_t)sidx[i + 1] * D4;
                const float4* r2 = caps4 + (size_t)sidx[i + 2] * D4;
                const float4* r3 = caps4 + (size_t)sidx[i + 3] * D4;
                float4 v0 = r0[tid];
                float4 v1 = r1[tid];
                float4 v2 = r2[tid];
                float4 v3 = r3[tid];
                acc.x += (v0.x + v1.x) + (v2.x + v3.x);
                acc.y += (v0.y + v1.y) + (v2.y + v3.y);
                acc.z += (v0.z + v1.z) + (v2.z + v3.z);
                acc.w += (v0.w + v1.w) + (v2.w + v3.w);
            }
            for (; i < n; ++i) {
                float4 v = caps4[(size_t)sidx[i] * D4 + tid];
                acc.x += v.x; acc.y += v.y; acc.z += v.z; acc.w += v.w;
            }
        }
        __syncthreads();
    }

    const float inv = 1.0f / fmaxf((float)(end - start), 1.0f);
    if (tid < D4) {
        pooled[4 * tid + 0] = acc.x * inv;
        pooled[4 * tid + 1] = acc.y * inv;
        pooled[4 * tid + 2] = acc.z * inv;
        pooled[4 * tid + 3] = acc.w * inv;
    }
    __syncthreads();

    if (tid < NC) {
        const int D = D4 * 4;
        float s = bias[tid];
        #pragma unroll 4
        for (int d = 0; d < D; ++d)
            s = fmaf(pooled[d], Wm[d * NC + tid], s);
        out[(size_t)seg * NC + tid] = 1.0f / (1.0f + __expf(-s));
    }
}

// Scalar fallback for arbitrary D (<= 2048 with BLOCK=256, 8 accumulators).
__global__ void __launch_bounds__(256)
capsule_scalar_kernel(const float* __restrict__ caps,
                      const float* __restrict__ Wm,
                      const float* __restrict__ bias,
                      const int* __restrict__ pidx,
                      float* __restrict__ out,
                      int D, int NC) {
    const int BLOCK = 256;
    const int seg = blockIdx.x;
    const int tid = threadIdx.x;
    const int start = g_seg_off[seg];
    const int end   = g_seg_off[seg + 1];

    __shared__ int sidx[256];
    extern __shared__ float pooled[];

    float acc[8];
    #pragma unroll
    for (int k = 0; k < 8; ++k) acc[k] = 0.f;

    for (int base = start; base < end; base += BLOCK) {
        int n = min(BLOCK, end - base);
        if (tid < n) sidx[tid] = pidx[base + tid];
        __syncthreads();
        for (int i = 0; i < n; ++i) {
            const float* row = caps + (size_t)sidx[i] * D;
            #pragma unroll
            for (int k = 0; k < 8; ++k) {
                int d = tid + k * BLOCK;
                if (d < D) acc[k] += row[d];
            }
        }
        __syncthreads();
    }

    const float inv = 1.0f / fmaxf((float)(end - start), 1.0f);
    #pragma unroll
    for (int k = 0; k < 8; ++k) {
        int d = tid + k * 256;
        if (d < D) pooled[d] = acc[k] * inv;
    }
    __syncthreads();

    if (tid < NC) {
        float s = bias[tid];
        for (int d = 0; d < D; ++d)
            s = fmaf(pooled[d], Wm[d * NC + tid], s);
        out[(size_t)seg * NC + tid] = 1.0f / (1.0f + __expf(-s));
    }
}

extern "C" void kernel_launch(void* const* d_in, const int* in_sizes, int n_in,
                              void* d_out, int out_size) {
    const float* caps  = (const float*)d_in[0];
    const float* Wm    = (const float*)d_in[1];
    const float* bias  = (const float*)d_in[2];
    const int*   pidx  = (const int*)d_in[3];
    const int*   segid = (const int*)d_in[4];
    float* out = (float*)d_out;

    const int NC = in_sizes[2];           // bias length
    const int D  = in_sizes[1] / NC;      // W is [D, NC]
    const int P  = in_sizes[3];           // point count
    const int NI = out_size / NC;         // number of segments

    seg_bounds_kernel<<<(P + 255) / 256, 256>>>(segid, P, NI);

    const int D4 = D / 4;
    if ((D & 3) == 0 && D4 <= 128) {
        capsule_vec_kernel<128><<<NI, 128, D * sizeof(float)>>>(
            (const float4*)caps, Wm, bias, pidx, out, D4, NC);
    } else if ((D & 3) == 0 && D4 <= 256) {
        capsule_vec_kernel<256><<<NI, 256, D * sizeof(float)>>>(
            (const float4*)caps, Wm, bias, pidx, out, D4, NC);
    } else {
        capsule_scalar_kernel<<<NI, 256, D * sizeof(float)>>>(
            caps, Wm, bias, pidx, out, D, NC);
    }
}

// round 4
// speedup vs baseline: 1.6706x; 1.6706x over previous
#include <cuda_runtime.h>
#include <math.h>

// ---------------------------------------------------------------------------
// CapsuleModel2: gather rows -> segment mean (sorted segment ids) -> GEMV ->
// sigmoid.
//   caps: [R, D] float32, W: [D, NC], b: [NC]
//   point_idx: [P] int32, segment_ids: [P] int32 sorted
//   out: [NI, NC] float32
//
// R1 -> R4 (R2/R3 never ran: broker timeouts):
//   - 4-team structure so ALL 256 threads gather (was 68/128)
//   - unroll-4 point loop per team (~1024 LDG.128 in flight per CTA)
//   - 8-threads-per-class parallel GEMV epilogue (was 19 serial dots)
//   - compile-time D4 specialization (D=272) strips predicates + IMADs
//   - pooled[] aliases sred[] (partials consumed before overwrite)
// ---------------------------------------------------------------------------

#define MAX_SEGS (1 << 17)
__device__ int g_seg_off[MAX_SEGS + 1];

__global__ void seg_bounds_kernel(const int* __restrict__ seg, int P, int NI) {
    int p = blockIdx.x * blockDim.x + threadIdx.x;
    if (p >= P) return;
    int s = seg[p];
    if (p == 0) {
        for (int k = 0; k <= s; ++k) g_seg_off[k] = 0;
    } else {
        int prev = seg[p - 1];
        for (int k = prev + 1; k <= s; ++k) g_seg_off[k] = p;
    }
    if (p == P - 1) {
        for (int k = s + 1; k <= NI; ++k) g_seg_off[k] = P;
    }
}

// Vector path: D % 4 == 0, D4 <= 128 (template D4). 256 threads = 4 teams
// x 64; thread owns col0 = lane64 and col1 = 64+lane64 (if < D4).
template <int D4>
__global__ void __launch_bounds__(256)
capsule_vec_kernel(const float4* __restrict__ caps4,
                   const float* __restrict__ Wm,
                   const float* __restrict__ bias,
                   const int* __restrict__ pidx,
                   float* __restrict__ out,
                   int NC) {
    const int seg    = blockIdx.x;
    const int tid    = threadIdx.x;
    const int team   = tid >> 6;         // 0..3
    const int lane64 = tid & 63;         // 0..63
    const int start  = g_seg_off[seg];
    const int end    = g_seg_off[seg + 1];

    const int col0 = lane64;             // always < 64 <= D4
    const int col1 = 64 + lane64;
    const bool has1 = col1 < D4;

    __shared__ int sidx[256];
    __shared__ float4 sred[D4 * 4];      // [D4][4] team partials
    float* pooled = (float*)sred;        // D floats, reused after consume

    float4 acc0 = make_float4(0.f, 0.f, 0.f, 0.f);
    float4 acc1 = make_float4(0.f, 0.f, 0.f, 0.f);

    for (int base = start; base < end; base += 256) {
        const int n = min(256, end - base);
        if (tid < n) sidx[tid] = pidx[base + tid];
        __syncthreads();

        int i = team;
        // unroll-4 over this team's points: 4-8 independent LDG.128/thread
        for (; i + 12 < n; i += 16) {
            const float4* r0 = caps4 + (size_t)sidx[i +  0] * D4;
            const float4* r1 = caps4 + (size_t)sidx[i +  4] * D4;
            const float4* r2 = caps4 + (size_t)sidx[i +  8] * D4;
            const float4* r3 = caps4 + (size_t)sidx[i + 12] * D4;
            float4 a0 = r0[col0], a1 = r1[col0], a2 = r2[col0], a3 = r3[col0];
            acc0.x += (a0.x + a1.x) + (a2.x + a3.x);
            acc0.y += (a0.y + a1.y) + (a2.y + a3.y);
            acc0.z += (a0.z + a1.z) + (a2.z + a3.z);
            acc0.w += (a0.w + a1.w) + (a2.w + a3.w);
            if (has1) {
                float4 b0 = r0[col1], b1 = r1[col1], b2 = r2[col1], b3 = r3[col1];
                acc1.x += (b0.x + b1.x) + (b2.x + b3.x);
                acc1.y += (b0.y + b1.y) + (b2.y + b3.y);
                acc1.z += (b0.z + b1.z) + (b2.z + b3.z);
                acc1.w += (b0.w + b1.w) + (b2.w + b3.w);
            }
        }
        for (; i < n; i += 4) {
            const float4* r = caps4 + (size_t)sidx[i] * D4;
            float4 v = r[col0];
            acc0.x += v.x; acc0.y += v.y; acc0.z += v.z; acc0.w += v.w;
            if (has1) {
                float4 w = r[col1];
                acc1.x += w.x; acc1.y += w.y; acc1.z += w.z; acc1.w += w.w;
            }
        }
        __syncthreads();
    }

    // team-partial reduction via smem
    sred[col0 * 4 + team] = acc0;
    if (has1) sred[col1 * 4 + team] = acc1;
    __syncthreads();

    const float inv = 1.0f / fmaxf((float)(end - start), 1.0f);
    float4 p4;
    if (tid < D4) {
        float4 s0 = sred[tid * 4 + 0];
        float4 s1 = sred[tid * 4 + 1];
        float4 s2 = sred[tid * 4 + 2];
        float4 s3 = sred[tid * 4 + 3];
        p4.x = ((s0.x + s1.x) + (s2.x + s3.x)) * inv;
        p4.y = ((s0.y + s1.y) + (s2.y + s3.y)) * inv;
        p4.z = ((s0.z + s1.z) + (s2.z + s3.z)) * inv;
        p4.w = ((s0.w + s1.w) + (s2.w + s3.w)) * inv;
    }
    __syncthreads();   // all partials consumed; safe to overwrite sred
    if (tid < D4) {
        pooled[4 * tid + 0] = p4.x;
        pooled[4 * tid + 1] = p4.y;
        pooled[4 * tid + 2] = p4.z;
        pooled[4 * tid + 3] = p4.w;
    }
    __syncthreads();

    // GEMV + sigmoid: 8 threads per class, shfl-reduce (8 | 32 so groups
    // never straddle a warp).
    const int c = tid >> 3;      // class
    const int j = tid & 7;       // sub-lane within class group
    if (c < NC) {
        const int D = D4 * 4;
        float s = (j == 0) ? bias[c] : 0.0f;
        for (int d = j; d < D; d += 8)
            s = fmaf(pooled[d], Wm[d * NC + c], s);
        s += __shfl_down_sync(0xFFFFFFFFu, s, 4);
        s += __shfl_down_sync(0xFFFFFFFFu, s, 2);
        s += __shfl_down_sync(0xFFFFFFFFu, s, 1);
        if (j == 0)
            out[(size_t)seg * NC + c] = 1.0f / (1.0f + __expf(-s));
    }
}

// Scalar fallback for arbitrary D (<= 2048).
__global__ void __launch_bounds__(256)
capsule_scalar_kernel(const float* __restrict__ caps,
                      const float* __restrict__ Wm,
                      const float* __restrict__ bias,
                      const int* __restrict__ pidx,
                      float* __restrict__ out,
                      int D, int NC) {
    const int BLOCK = 256;
    const int seg = blockIdx.x;
    const int tid = threadIdx.x;
    const int start = g_seg_off[seg];
    const int end   = g_seg_off[seg + 1];

    __shared__ int sidx[256];
    extern __shared__ float pooled[];

    float acc[8];
    #pragma unroll
    for (int k = 0; k < 8; ++k) acc[k] = 0.f;

    for (int base = start; base < end; base += BLOCK) {
        int n = min(BLOCK, end - base);
        if (tid < n) sidx[tid] = pidx[base + tid];
        __syncthreads();
        for (int i = 0; i < n; ++i) {
            const float* row = caps + (size_t)sidx[i] * D;
            #pragma unroll
            for (int k = 0; k < 8; ++k) {
                int d = tid + k * BLOCK;
                if (d < D) acc[k] += row[d];
            }
        }
        __syncthreads();
    }

    const float inv = 1.0f / fmaxf((float)(end - start), 1.0f);
    #pragma unroll
    for (int k = 0; k < 8; ++k) {
        int d = tid + k * 256;
        if (d < D) pooled[d] = acc[k] * inv;
    }
    __syncthreads();

    if (tid < NC) {
        float s = bias[tid];
        for (int d = 0; d < D; ++d)
            s = fmaf(pooled[d], Wm[d * NC + tid], s);
        out[(size_t)seg * NC + tid] = 1.0f / (1.0f + __expf(-s));
    }
}

extern "C" void kernel_launch(void* const* d_in, const int* in_sizes, int n_in,
                              void* d_out, int out_size) {
    const float* caps  = (const float*)d_in[0];
    const float* Wm    = (const float*)d_in[1];
    const float* bias  = (const float*)d_in[2];
    const int*   pidx  = (const int*)d_in[3];
    const int*   segid = (const int*)d_in[4];
    float* out = (float*)d_out;

    const int NC = in_sizes[2];
    const int D  = in_sizes[1] / NC;
    const int P  = in_sizes[3];
    const int NI = out_size / NC;

    seg_bounds_kernel<<<(P + 255) / 256, 256>>>(segid, P, NI);

    if (D == 272) {
        capsule_vec_kernel<68><<<NI, 256>>>(
            (const float4*)caps, Wm, bias, pidx, out, NC);
    } else if (D == 256) {
        capsule_vec_kernel<64><<<NI, 256>>>(
            (const float4*)caps, Wm, bias, pidx, out, NC);
    } else if (D == 512) {
        capsule_vec_kernel<128><<<NI, 256>>>(
            (const float4*)caps, Wm, bias, pidx, out, NC);
    } else {
        capsule_scalar_kernel<<<NI, 256, D * sizeof(float)>>>(
            caps, Wm, bias, pidx, out, D, NC);
    }
}

// round 5
// speedup vs baseline: 1.7371x; 1.0398x over previous
#include <cuda_runtime.h>
#include <math.h>

// ---------------------------------------------------------------------------
// CapsuleModel2: out = sigmoid(mean_seg(caps[pidx]) @ W + b)
//
// R4 -> R5 ALGORITHMIC RESTRUCTURE: mean(feats) @ W == mean(feats @ W), so
//   phase 1: proj[R,20] = caps[R,272] @ W[272,19]  (pad to 20; f32x2 FMA2)
//   phase 2: per-segment gather-sum of 19-float proj rows (+bias, sigmoid)
// Gather traffic drops 570MB -> ~50MB; GEMM reads the 71MB tensor once.
// ---------------------------------------------------------------------------

#define MAX_SEGS (1 << 17)
#define MAX_R    65536
__device__ int   g_seg_off[MAX_SEGS + 1];
__device__ float g_proj[(size_t)MAX_R * 20];

// ---------------------------------------------------------------- f32x2 utils
__device__ __forceinline__ unsigned long long dup_f32(float x) {
    unsigned long long r;
    unsigned int u = __float_as_uint(x);
    asm("mov.b64 %0, {%1, %1};" : "=l"(r) : "r"(u));
    return r;
}
__device__ __forceinline__ void fma2(unsigned long long& d,
                                     unsigned long long a,
                                     unsigned long long b) {
    asm("fma.rn.f32x2 %0, %1, %2, %0;" : "+l"(d) : "l"(a), "l"(b));
}
__device__ __forceinline__ float2 unpack2(unsigned long long v) {
    unsigned int lo, hi;
    asm("mov.b64 {%0, %1}, %2;" : "=r"(lo), "=r"(hi) : "l"(v));
    return make_float2(__uint_as_float(lo), __uint_as_float(hi));
}

// ---------------------------------------------------------------- seg bounds
__global__ void seg_bounds_kernel(const int* __restrict__ seg, int P, int NI) {
    int p = blockIdx.x * blockDim.x + threadIdx.x;
    if (p >= P) return;
    int s = seg[p];
    if (p == 0) {
        for (int k = 0; k <= s; ++k) g_seg_off[k] = 0;
    } else {
        int prev = seg[p - 1];
        for (int k = prev + 1; k <= s; ++k) g_seg_off[k] = p;
    }
    if (p == P - 1) {
        for (int k = s + 1; k <= NI; ++k) g_seg_off[k] = P;
    }
}

// ---------------------------------------------------------------- phase 1
// proj = caps @ W for D=272, NC=19(->20). Tile 64 rows; 160 threads =
// 32 row-slots x 5 pair-groups; thread owns rows (rs, rs+32) and class-pairs
// (g, g+5). W staged as [272][20] (pairs LDS.64, warp-uniform -> broadcast).
// caps staged as float4 [64][69] (odd stride -> conflict-free LDS.128).
#define P1_BLOCK 160
#define P1_TILE  64
#define P1_SMEM  (P1_TILE * 69 * 16 + 272 * 20 * 4)

__global__ void __launch_bounds__(P1_BLOCK)
proj_kernel(const float4* __restrict__ caps4,   // [R][68]
            const float*  __restrict__ Wm,      // [272][19]
            int ntiles) {
    extern __shared__ float sm[];
    float4* caps_s = (float4*)sm;               // [64][69]
    float*  Ws     = sm + P1_TILE * 69 * 4;     // [272][20]

    const int tid = threadIdx.x;

    // stage W once per CTA (zero-pad class 19)
    for (int i = tid; i < 272 * 20; i += P1_BLOCK) {
        int d = i / 20, c = i % 20;
        Ws[i] = (c < 19) ? Wm[d * 19 + c] : 0.0f;
    }

    const int rs = tid & 31;          // row slot
    const int g  = tid >> 5;          // pair group 0..4
    const int p0 = g, p1 = g + 5;     // class pairs

    for (int tile = blockIdx.x; tile < ntiles; tile += gridDim.x) {
        __syncthreads();              // previous compute done with caps_s
        // stage 64 rows, coalesced
        const float4* src = caps4 + (size_t)tile * P1_TILE * 68;
        for (int i = tid; i < P1_TILE * 68; i += P1_BLOCK) {
            int r = i / 68, d4 = i % 68;
            caps_s[r * 69 + d4] = src[(size_t)r * 68 + d4];
        }
        __syncthreads();

        unsigned long long a00 = 0ull, a01 = 0ull, a10 = 0ull, a11 = 0ull;
        const float4* row0 = caps_s + rs * 69;
        const float4* row1 = caps_s + (rs + 32) * 69;

        #pragma unroll 4
        for (int d4 = 0; d4 < 68; ++d4) {
            float4 v0 = row0[d4];
            float4 v1 = row1[d4];
            const float* wd = Ws + d4 * 4 * 20;
            #pragma unroll
            for (int j = 0; j < 4; ++j) {
                float x0 = (j == 0) ? v0.x : (j == 1) ? v0.y : (j == 2) ? v0.z : v0.w;
                float x1 = (j == 0) ? v1.x : (j == 1) ? v1.y : (j == 2) ? v1.z : v1.w;
                unsigned long long b0 = dup_f32(x0);
                unsigned long long b1 = dup_f32(x1);
                unsigned long long w0 = *(const unsigned long long*)(wd + j * 20 + 2 * p0);
                unsigned long long w1 = *(const unsigned long long*)(wd + j * 20 + 2 * p1);
                fma2(a00, b0, w0);
                fma2(a01, b0, w1);
                fma2(a10, b1, w0);
                fma2(a11, b1, w1);
            }
        }

        // writeout: rows tile*64+rs, tile*64+rs+32; classes 2p0..2p0+1, 2p1..2p1+1
        const size_t gr0 = ((size_t)tile * P1_TILE + rs) * 20;
        const size_t gr1 = gr0 + 32 * 20;
        float2 f00 = unpack2(a00), f01 = unpack2(a01);
        float2 f10 = unpack2(a10), f11 = unpack2(a11);
        g_proj[gr0 + 2 * p0]     = f00.x;
        g_proj[gr0 + 2 * p0 + 1] = f00.y;
        g_proj[gr0 + 2 * p1]     = f01.x;
        g_proj[gr0 + 2 * p1 + 1] = f01.y;
        g_proj[gr1 + 2 * p0]     = f10.x;
        g_proj[gr1 + 2 * p0 + 1] = f10.y;
        g_proj[gr1 + 2 * p1]     = f11.x;
        g_proj[gr1 + 2 * p1 + 1] = f11.y;
    }
}

// ---------------------------------------------------------------- phase 2
// One CTA (128 thr) per segment. 8 lanes per point, 5 active lanes read the
// point's 5 float4 (contiguous 80B row -> 1-2 lines per point).
__global__ void __launch_bounds__(128)
pool_kernel(const int* __restrict__ pidx,
            const float* __restrict__ bias,
            float* __restrict__ out) {
    const int seg   = blockIdx.x;
    const int tid   = threadIdx.x;
    const int grp   = tid >> 3;       // 0..15
    const int sub   = tid & 7;        // f4 slot if < 5
    const int start = g_seg_off[seg];
    const int end   = g_seg_off[seg + 1];

    const float4* proj4 = (const float4*)g_proj;
    float4 acc = make_float4(0.f, 0.f, 0.f, 0.f);

    for (int p = start + grp; p < end; p += 16) {
        int row = __ldg(&pidx[p]);
        if (sub < 5) {
            float4 v = proj4[(size_t)row * 5 + sub];
            acc.x += v.x; acc.y += v.y; acc.z += v.z; acc.w += v.w;
        }
    }

    // reduce the 4 groups within each warp (lanes l, l+8, l+16, l+24)
    #pragma unroll
    for (int off = 16; off >= 8; off >>= 1) {
        acc.x += __shfl_down_sync(0xFFFFFFFFu, acc.x, off);
        acc.y += __shfl_down_sync(0xFFFFFFFFu, acc.y, off);
        acc.z += __shfl_down_sync(0xFFFFFFFFu, acc.z, off);
        acc.w += __shfl_down_sync(0xFFFFFFFFu, acc.w, off);
    }

    __shared__ float wt[4][32];       // 4 warps x 8 slots x 4 comps
    const int lane = tid & 31, w = tid >> 5;
    if (lane < 8) {
        wt[w][lane * 4 + 0] = acc.x;
        wt[w][lane * 4 + 1] = acc.y;
        wt[w][lane * 4 + 2] = acc.z;
        wt[w][lane * 4 + 3] = acc.w;
    }
    __syncthreads();

    if (tid < 19) {
        const float inv = 1.0f / fmaxf((float)(end - start), 1.0f);
        float s = wt[0][tid] + wt[1][tid] + wt[2][tid] + wt[3][tid];
        float logit = s * inv + bias[tid];
        out[(size_t)seg * 19 + tid] = 1.0f / (1.0f + __expf(-logit));
    }
}

// ================================================================ fallback
// (proven 60us path, kept for non-matching shapes)
template <int D4>
__global__ void __launch_bounds__(256)
capsule_vec_kernel(const float4* __restrict__ caps4,
                   const float* __restrict__ Wm,
                   const float* __restrict__ bias,
                   const int* __restrict__ pidx,
                   float* __restrict__ out,
                   int NC) {
    const int seg    = blockIdx.x;
    const int tid    = threadIdx.x;
    const int team   = tid >> 6;
    const int lane64 = tid & 63;
    const int start  = g_seg_off[seg];
    const int end    = g_seg_off[seg + 1];

    const int col0 = lane64;
    const int col1 = 64 + lane64;
    const bool has1 = col1 < D4;

    __shared__ int sidx[256];
    __shared__ float4 sred[D4 * 4];
    float* pooled = (float*)sred;

    float4 acc0 = make_float4(0.f, 0.f, 0.f, 0.f);
    float4 acc1 = make_float4(0.f, 0.f, 0.f, 0.f);

    for (int base = start; base < end; base += 256) {
        const int n = min(256, end - base);
        if (tid < n) sidx[tid] = pidx[base + tid];
        __syncthreads();
        int i = team;
        for (; i + 12 < n; i += 16) {
            const float4* r0 = caps4 + (size_t)sidx[i +  0] * D4;
            const float4* r1 = caps4 + (size_t)sidx[i +  4] * D4;
            const float4* r2 = caps4 + (size_t)sidx[i +  8] * D4;
            const float4* r3 = caps4 + (size_t)sidx[i + 12] * D4;
            float4 a0 = r0[col0], a1 = r1[col0], a2 = r2[col0], a3 = r3[col0];
            acc0.x += (a0.x + a1.x) + (a2.x + a3.x);
            acc0.y += (a0.y + a1.y) + (a2.y + a3.y);
            acc0.z += (a0.z + a1.z) + (a2.z + a3.z);
            acc0.w += (a0.w + a1.w) + (a2.w + a3.w);
            if (has1) {
                float4 b0 = r0[col1], b1 = r1[col1], b2 = r2[col1], b3 = r3[col1];
                acc1.x += (b0.x + b1.x) + (b2.x + b3.x);
                acc1.y += (b0.y + b1.y) + (b2.y + b3.y);
                acc1.z += (b0.z + b1.z) + (b2.z + b3.z);
                acc1.w += (b0.w + b1.w) + (b2.w + b3.w);
            }
        }
        for (; i < n; i += 4) {
            const float4* r = caps4 + (size_t)sidx[i] * D4;
            float4 v = r[col0];
            acc0.x += v.x; acc0.y += v.y; acc0.z += v.z; acc0.w += v.w;
            if (has1) {
                float4 w = r[col1];
                acc1.x += w.x; acc1.y += w.y; acc1.z += w.z; acc1.w += w.w;
            }
        }
        __syncthreads();
    }

    sred[col0 * 4 + team] = acc0;
    if (has1) sred[col1 * 4 + team] = acc1;
    __syncthreads();

    const float inv = 1.0f / fmaxf((float)(end - start), 1.0f);
    float4 p4;
    if (tid < D4) {
        float4 s0 = sred[tid * 4 + 0];
        float4 s1 = sred[tid * 4 + 1];
        float4 s2 = sred[tid * 4 + 2];
        float4 s3 = sred[tid * 4 + 3];
        p4.x = ((s0.x + s1.x) + (s2.x + s3.x)) * inv;
        p4.y = ((s0.y + s1.y) + (s2.y + s3.y)) * inv;
        p4.z = ((s0.z + s1.z) + (s2.z + s3.z)) * inv;
        p4.w = ((s0.w + s1.w) + (s2.w + s3.w)) * inv;
    }
    __syncthreads();
    if (tid < D4) {
        pooled[4 * tid + 0] = p4.x;
        pooled[4 * tid + 1] = p4.y;
        pooled[4 * tid + 2] = p4.z;
        pooled[4 * tid + 3] = p4.w;
    }
    __syncthreads();

    const int c = tid >> 3;
    const int j = tid & 7;
    if (c < NC) {
        const int D = D4 * 4;
        float s = (j == 0) ? bias[c] : 0.0f;
        for (int d = j; d < D; d += 8)
            s = fmaf(pooled[d], Wm[d * NC + c], s);
        s += __shfl_down_sync(0xFFFFFFFFu, s, 4);
        s += __shfl_down_sync(0xFFFFFFFFu, s, 2);
        s += __shfl_down_sync(0xFFFFFFFFu, s, 1);
        if (j == 0)
            out[(size_t)seg * NC + c] = 1.0f / (1.0f + __expf(-s));
    }
}

__global__ void __launch_bounds__(256)
capsule_scalar_kernel(const float* __restrict__ caps,
                      const float* __restrict__ Wm,
                      const float* __restrict__ bias,
                      const int* __restrict__ pidx,
                      float* __restrict__ out,
                      int D, int NC) {
    const int BLOCK = 256;
    const int seg = blockIdx.x;
    const int tid = threadIdx.x;
    const int start = g_seg_off[seg];
    const int end   = g_seg_off[seg + 1];

    __shared__ int sidx[256];
    extern __shared__ float pooled[];

    float acc[8];
    #pragma unroll
    for (int k = 0; k < 8; ++k) acc[k] = 0.f;

    for (int base = start; base < end; base += BLOCK) {
        int n = min(BLOCK, end - base);
        if (tid < n) sidx[tid] = pidx[base + tid];
        __syncthreads();
        for (int i = 0; i < n; ++i) {
            const float* row = caps + (size_t)sidx[i] * D;
            #pragma unroll
            for (int k = 0; k < 8; ++k) {
                int d = tid + k * BLOCK;
                if (d < D) acc[k] += row[d];
            }
        }
        __syncthreads();
    }

    const float inv = 1.0f / fmaxf((float)(end - start), 1.0f);
    #pragma unroll
    for (int k = 0; k < 8; ++k) {
        int d = tid + k * 256;
        if (d < D) pooled[d] = acc[k] * inv;
    }
    __syncthreads();

    if (tid < NC) {
        float s = bias[tid];
        for (int d = 0; d < D; ++d)
            s = fmaf(pooled[d], Wm[d * NC + tid], s);
        out[(size_t)seg * NC + tid] = 1.0f / (1.0f + __expf(-s));
    }
}

// ================================================================ launch
extern "C" void kernel_launch(void* const* d_in, const int* in_sizes, int n_in,
                              void* d_out, int out_size) {
    const float* caps  = (const float*)d_in[0];
    const float* Wm    = (const float*)d_in[1];
    const float* bias  = (const float*)d_in[2];
    const int*   pidx  = (const int*)d_in[3];
    const int*   segid = (const int*)d_in[4];
    float* out = (float*)d_out;

    const int NC = in_sizes[2];
    const int D  = in_sizes[1] / NC;
    const int P  = in_sizes[3];
    const int NI = out_size / NC;
    const int R  = in_sizes[0] / D;

    seg_bounds_kernel<<<(P + 255) / 256, 256>>>(segid, P, NI);

    if (D == 272 && NC == 19 && R <= MAX_R && (R % P1_TILE) == 0) {
        cudaFuncSetAttribute(proj_kernel,
                             cudaFuncAttributeMaxDynamicSharedMemorySize,
                             P1_SMEM);
        proj_kernel<<<296, P1_BLOCK, P1_SMEM>>>(
            (const float4*)caps, Wm, R / P1_TILE);
        pool_kernel<<<NI, 128>>>(pidx, bias, out);
    } else if (D == 272) {
        capsule_vec_kernel<68><<<NI, 256>>>(
            (const float4*)caps, Wm, bias, pidx, out, NC);
    } else if (D == 256) {
        capsule_vec_kernel<64><<<NI, 256>>>(
            (const float4*)caps, Wm, bias, pidx, out, NC);
    } else {
        capsule_scalar_kernel<<<NI, 256, D * sizeof(float)>>>(
            caps, Wm, bias, pidx, out, D, NC);
    }
}